// round 15
// baseline (speedup 1.0000x reference)
#include <cuda_runtime.h>
#include <cuda_fp16.h>
#include <math.h>
#include <stdint.h>

// ---------------- problem constants ----------------
#define B_SZ     2
#define L_SZ     1024
#define DMODEL   2048
#define DINNER   4096
#define DSTATE   16
#define DCONV    4
#define DTRANK   128
#define XDBL_K   160
#define NROWS    2048

#define XSPLIT   8             // split-K factor for x_proj

// extended-K sizes
#define KE_IN    DMODEL        // 2048   plain fp16 (1-term)
#define KE_X     (3*DINNER)    // 12288  A [hi|lo|hi], B [hi|hi|lo]
#define KE_DT    (3*DTRANK)    // 384    A [hi|lo|hi], B [hi|hi|lo]
#define KE_OUT   DINNER        // 4096   plain fp16 (1-term)

// ---------------- scratch (__device__ globals, no allocation) ----------------
__device__ float g_xz   [(size_t)NROWS * 2 * DINNER];
__device__ float g_xconv[(size_t)NROWS * DINNER];
__device__ float g_bc   [(size_t)NROWS * 2 * DSTATE];   // interleaved (B,C)
__device__ float g_xpart[(size_t)XSPLIT * NROWS * XDBL_K];
__device__ float g_delta[(size_t)NROWS * DINNER];
__device__ float g_y    [(size_t)NROWS * DINNER];

__device__ __align__(16) __half g_hid_e [(size_t)NROWS    * KE_IN ];
__device__ __align__(16) __half g_win_e [(size_t)2*DINNER * KE_IN ];
__device__ __align__(16) __half g_xc_e  [(size_t)NROWS    * KE_X  ];
__device__ __align__(16) __half g_xw_e  [(size_t)256      * KE_X  ];
__device__ __align__(16) __half g_dtlo_e[(size_t)NROWS    * KE_DT ];
__device__ __align__(16) __half g_dtw_e [(size_t)DINNER   * KE_DT ];
__device__ __align__(16) __half g_yb_e  [(size_t)NROWS    * KE_OUT];
__device__ __align__(16) __half g_ow_e  [(size_t)DMODEL   * KE_OUT];

// ---------------- PTX helpers (baseline ISA: sm_80+ mma.sync / cp.async) ------
__device__ __forceinline__ uint32_t smem_u32(const void* p) {
    uint32_t a;
    asm("{ .reg .u64 t; cvta.to.shared.u64 t, %1; cvt.u32.u64 %0, t; }"
        : "=r"(a) : "l"(p));
    return a;
}

#define CP_ASYNC16(sa, ga) \
    asm volatile("cp.async.cg.shared.global [%0], [%1], 16;" \
                 :: "r"(sa), "l"(ga) : "memory")
#define CP_COMMIT() asm volatile("cp.async.commit_group;" ::: "memory")
#define CP_WAIT(N)  asm volatile("cp.async.wait_group %0;" :: "n"(N) : "memory")

#define LDSM_X4(R0, R1, R2, R3, ADDR) \
    asm volatile("ldmatrix.sync.aligned.m8n8.x4.shared.b16 {%0,%1,%2,%3}, [%4];" \
                 : "=r"(R0), "=r"(R1), "=r"(R2), "=r"(R3) : "r"(ADDR))

#define MMA16816(C, A0, A1, A2, A3, B0, B1) \
    asm volatile("mma.sync.aligned.m16n8k16.row.col.f32.f16.f16.f32 " \
                 "{%0,%1,%2,%3}, {%4,%5,%6,%7}, {%8,%9}, {%0,%1,%2,%3};" \
                 : "+f"((C)[0]), "+f"((C)[1]), "+f"((C)[2]), "+f"((C)[3]) \
                 : "r"(A0), "r"(A1), "r"(A2), "r"(A3), "r"(B0), "r"(B1))

// ---------------- HMMA GEMM: C = A[M,Kext]*B[N,Kext]^T ----------------------
#define BM 128
#define BN 256
#define BK 32
#define STAGES 4
#define LDS_ROW 40
#define A_TILE_BYTES (BM * LDS_ROW * 2)            // 10240
#define B_TILE_BYTES (BN * LDS_ROW * 2)            // 20480
#define STAGE_BYTES  (A_TILE_BYTES + B_TILE_BYTES) // 30720
#define GEMM_SMEM (STAGES * STAGE_BYTES)           // 122880

template<int ACT>
__global__ void __launch_bounds__(256, 1)
gemm_mma(const __half* __restrict__ A,
         const __half* __restrict__ B,
         float* __restrict__ C, int ldc,
         int Nact, int Kext, int kIters, size_t partStride,
         const float* __restrict__ bias)
{
    extern __shared__ char smem[];
    const uint32_t sbase = smem_u32(smem);

    const int t    = threadIdx.x;
    const int lane = t & 31;
    const int wid  = t >> 5;
    const int wm   = wid >> 2;
    const int wn   = wid & 3;
    const int m0   = blockIdx.x * BM;
    const int n0   = blockIdx.y * BN;
    const size_t kbase = (size_t)blockIdx.z * kIters * BK;
    C += (size_t)blockIdx.z * partStride;

    const int ra0 = t >> 2,          ca0 = t & 3;
    const int ra1 = (t + 256) >> 2,  ca1 = (t + 256) & 3;
    const __half* gA0 = A + (size_t)(m0 + ra0) * Kext + kbase + ca0 * 8;
    const __half* gA1 = A + (size_t)(m0 + ra1) * Kext + kbase + ca1 * 8;
    const uint32_t sAo0 = (uint32_t)(ra0 * LDS_ROW * 2 + ca0 * 16);
    const uint32_t sAo1 = (uint32_t)(ra1 * LDS_ROW * 2 + ca1 * 16);
    const __half* gB[4];
    uint32_t sBo[4];
    #pragma unroll
    for (int q = 0; q < 4; q++) {
        int id = t + q * 256;
        int rr = id >> 2, cc = id & 3;
        gB[q]  = B + (size_t)(n0 + rr) * Kext + kbase + cc * 8;
        sBo[q] = (uint32_t)(rr * LDS_ROW * 2 + cc * 16);
    }

    const int g = lane >> 3, r = lane & 7;
    const uint32_t a_off = (uint32_t)((wm * 64 + (g & 1) * 8 + r) * LDS_ROW * 2
                                      + ((g >> 1) * 8) * 2);
    const uint32_t b_off = (uint32_t)((wn * 64 + (g >> 1) * 8 + r) * LDS_ROW * 2
                                      + ((g & 1) * 8) * 2);

    float acc[4][8][4];
    #pragma unroll
    for (int i = 0; i < 4; i++)
        #pragma unroll
        for (int j = 0; j < 8; j++)
            #pragma unroll
            for (int e = 0; e < 4; e++) acc[i][j][e] = 0.f;

    #pragma unroll
    for (int s = 0; s < STAGES - 1; s++) {
        const size_t k0 = (size_t)s * BK;
        const uint32_t st = sbase + s * STAGE_BYTES;
        CP_ASYNC16(st + sAo0, gA0 + k0);
        CP_ASYNC16(st + sAo1, gA1 + k0);
        #pragma unroll
        for (int q = 0; q < 4; q++)
            CP_ASYNC16(st + A_TILE_BYTES + sBo[q], gB[q] + k0);
        CP_COMMIT();
    }

    for (int it = 0; it < kIters; it++) {
        CP_WAIT(STAGES - 2);
        __syncthreads();

        if (it + STAGES - 1 < kIters) {
            const size_t k0 = (size_t)(it + STAGES - 1) * BK;
            const uint32_t st = sbase + ((it + STAGES - 1) % STAGES) * STAGE_BYTES;
            CP_ASYNC16(st + sAo0, gA0 + k0);
            CP_ASYNC16(st + sAo1, gA1 + k0);
            #pragma unroll
            for (int q = 0; q < 4; q++)
                CP_ASYNC16(st + A_TILE_BYTES + sBo[q], gB[q] + k0);
        }
        CP_COMMIT();

        const uint32_t sa  = sbase + (it % STAGES) * STAGE_BYTES;
        const uint32_t sbb = sa + A_TILE_BYTES;
        #pragma unroll
        for (int ks = 0; ks < 2; ks++) {
            uint32_t af[4][4], bfr[4][4];
            #pragma unroll
            for (int i = 0; i < 4; i++)
                LDSM_X4(af[i][0], af[i][1], af[i][2], af[i][3],
                        sa + a_off + ks * 32 + i * (16 * LDS_ROW * 2));
            #pragma unroll
            for (int jp = 0; jp < 4; jp++)
                LDSM_X4(bfr[jp][0], bfr[jp][1], bfr[jp][2], bfr[jp][3],
                        sbb + b_off + ks * 32 + jp * (16 * LDS_ROW * 2));
            #pragma unroll
            for (int i = 0; i < 4; i++)
                #pragma unroll
                for (int j = 0; j < 8; j++)
                    MMA16816(acc[i][j], af[i][0], af[i][1], af[i][2], af[i][3],
                             bfr[j >> 1][(j & 1) * 2], bfr[j >> 1][(j & 1) * 2 + 1]);
        }
    }

    #pragma unroll
    for (int i = 0; i < 4; i++) {
        const int m = m0 + wm * 64 + i * 16 + (lane >> 2);
        #pragma unroll
        for (int j = 0; j < 8; j++) {
            const int n = n0 + wn * 64 + j * 8 + (lane & 3) * 2;
            #pragma unroll
            for (int e = 0; e < 4; e++) {
                const int mm = m + (e >> 1) * 8;
                const int nn = n + (e & 1);
                if (nn < Nact) {
                    float v = acc[i][j][e];
                    if (ACT == 1) {
                        v += bias[nn];
                        v = (v > 20.f) ? v : __logf(1.f + __expf(v));
                    }
                    C[(size_t)mm * ldc + nn] = v;
                }
            }
        }
    }
}

// ---------------- fp32 -> fp16 conversion (vectorized, 8 elems/thread) -------
template<int PAT>
__global__ void cvt_w(const float* __restrict__ in, int ldin, int Kin,
                      __half* __restrict__ out, int R)
{
    int k = (blockIdx.x * blockDim.x + threadIdx.x) * 8;
    int r = blockIdx.y;
    if (k >= Kin) return;
    float v[8];
    if (r < R) {
        float4 a = *(const float4*)(in + (size_t)r * ldin + k);
        float4 b = *(const float4*)(in + (size_t)r * ldin + k + 4);
        v[0]=a.x; v[1]=a.y; v[2]=a.z; v[3]=a.w;
        v[4]=b.x; v[5]=b.y; v[6]=b.z; v[7]=b.w;
    } else {
        #pragma unroll
        for (int j = 0; j < 8; j++) v[j] = 0.f;
    }
    __align__(16) __half h[8];
    #pragma unroll
    for (int j = 0; j < 8; j++) h[j] = __float2half(v[j]);
    if (PAT == 0) {
        *(uint4*)(out + (size_t)r * Kin + k) = *(uint4*)h;
    } else {
        __align__(16) __half l[8];
        #pragma unroll
        for (int j = 0; j < 8; j++) l[j] = __float2half(v[j] - __half2float(h[j]));
        size_t o = (size_t)r * 3 * Kin;
        *(uint4*)(out + o + k)           = *(uint4*)h;
        *(uint4*)(out + o + Kin + k)     = *(uint4*)h;
        *(uint4*)(out + o + 2 * Kin + k) = *(uint4*)l;
    }
}

// ---------------- conv1d + bias + SiLU, x4 vectorized, fused [hi|lo|hi] ------
__global__ void conv_silu_kernel(const float* __restrict__ xz,
                                 const float* __restrict__ cw,
                                 const float* __restrict__ cb,
                                 float* __restrict__ xc,
                                 __half* __restrict__ xce)
{
    int gidx = blockIdx.x * blockDim.x + threadIdx.x;
    int base = gidx * 4;
    int d  = base & (DINNER - 1);
    int bl = base >> 12;
    int l  = bl & (L_SZ - 1);
    int b  = bl >> 10;

    float4 cbv = *(const float4*)(cb + d);
    float a[4] = {cbv.x, cbv.y, cbv.z, cbv.w};
    float4 w[4];
    #pragma unroll
    for (int dd = 0; dd < 4; dd++) w[dd] = *(const float4*)(cw + (d + dd) * DCONV);

    #pragma unroll
    for (int j = 0; j < DCONV; j++) {
        int l2 = l - (DCONV - 1) + j;
        if (l2 >= 0) {
            float4 x4 = *(const float4*)(xz + (size_t)(b * L_SZ + l2) * (2 * DINNER) + d);
            a[0] = fmaf(x4.x, ((const float*)&w[0])[j], a[0]);
            a[1] = fmaf(x4.y, ((const float*)&w[1])[j], a[1]);
            a[2] = fmaf(x4.z, ((const float*)&w[2])[j], a[2]);
            a[3] = fmaf(x4.w, ((const float*)&w[3])[j], a[3]);
        }
    }
    float v[4];
    #pragma unroll
    for (int dd = 0; dd < 4; dd++) v[dd] = a[dd] / (1.f + __expf(-a[dd]));

    *(float4*)(xc + (size_t)bl * DINNER + d) = make_float4(v[0], v[1], v[2], v[3]);

    __half h[4], lo[4];
    #pragma unroll
    for (int dd = 0; dd < 4; dd++) {
        h[dd]  = __float2half(v[dd]);
        lo[dd] = __float2half(v[dd] - __half2float(h[dd]));
    }
    size_t o = (size_t)bl * KE_X + d;
    *(uint2*)(xce + o)              = *(uint2*)h;
    *(uint2*)(xce + o + DINNER)     = *(uint2*)lo;
    *(uint2*)(xce + o + 2 * DINNER) = *(uint2*)h;
}

// ---------------- split-K reduce: emits dt_lo [hi|lo|hi] + interleaved BC ----
__global__ void reduce_split(const float* __restrict__ part,
                             __half* __restrict__ dtlo,
                             float* __restrict__ bc, int n)
{
    int i = blockIdx.x * blockDim.x + threadIdx.x;
    if (i >= n) return;
    float s = 0.f;
    #pragma unroll
    for (int p = 0; p < XSPLIT; p++) s += part[(size_t)p * n + i];
    int r = i / XDBL_K;
    int k = i - r * XDBL_K;
    if (k < DTRANK) {
        __half h = __float2half(s);
        __half lo = __float2half(s - __half2float(h));
        size_t o = (size_t)r * KE_DT + k;
        dtlo[o] = h;
        dtlo[o + DTRANK] = lo;
        dtlo[o + 2 * DTRANK] = h;
    } else if (k < DTRANK + DSTATE) {
        bc[(size_t)r * 2 * DSTATE + 2 * (k - DTRANK)] = s;
    } else {
        bc[(size_t)r * 2 * DSTATE + 2 * (k - DTRANK - DSTATE) + 1] = s;
    }
}

// ---------------- selective scan: 16 lanes/channel, T=8 timestep batching ----
// Same decomposition and bit-identical math as the R13 scan (verified win);
// batch widened 4 -> 8 so each butterfly stage pipelines 8 independent shfls
// and the dependent-latency chain is paid once per 8 timesteps.
__global__ void scan_kernel(const float* __restrict__ delta,
                            const float* __restrict__ bc,
                            const float* __restrict__ xconv,
                            const float* __restrict__ A_log,
                            float* __restrict__ y)
{
    int n   = threadIdx.x & 15;
    int grp = (blockIdx.x * blockDim.x + threadIdx.x) >> 4;
    int b   = grp >> 12;
    int d   = grp & (DINNER - 1);

    float a = -expf(A_log[d * DSTATE + n]);
    float h = 0.f;
    size_t base = (size_t)b * L_SZ;
    const float2* bc2 = (const float2*)bc;

    for (int l0 = 0; l0 < L_SZ; l0 += 8) {
        float p[8];
        #pragma unroll
        for (int t = 0; t < 8; t++) {
            size_t r = base + l0 + t;
            float dv = delta[r * DINNER + d];
            float xv = xconv[r * DINNER + d];
            float2 BC = bc2[r * DSTATE + n];

            float dA = __expf(dv * a);
            h = fmaf(h, dA, dv * BC.x * xv);
            p[t] = h * BC.y;
        }
        #pragma unroll
        for (int s = 8; s >= 1; s >>= 1) {
            #pragma unroll
            for (int t = 0; t < 8; t++)
                p[t] += __shfl_xor_sync(0xffffffffu, p[t], s, 16);
        }
        if (n == 0) {
            #pragma unroll
            for (int t = 0; t < 8; t++)
                y[(base + l0 + t) * DINNER + d] = p[t];
        }
    }
}

// ---------------- y = (y + x*D) * silu(z), x4 vectorized, fp16 emit ----------
__global__ void ymod_kernel(const float* __restrict__ y,
                            const float* __restrict__ xconv,
                            const float* __restrict__ Dv,
                            const float* __restrict__ xz,
                            __half* __restrict__ ybe)
{
    int gidx = blockIdx.x * blockDim.x + threadIdx.x;
    int base = gidx * 4;
    int d = base & (DINNER - 1);
    int r = base >> 12;

    float4 zv = *(const float4*)(xz + (size_t)r * (2 * DINNER) + DINNER + d);
    float4 yv = *(const float4*)(y + (size_t)r * DINNER + d);
    float4 xv = *(const float4*)(xconv + (size_t)r * DINNER + d);
    float4 dv = *(const float4*)(Dv + d);

    float v[4];
    v[0] = (yv.x + xv.x * dv.x) * (zv.x / (1.f + __expf(-zv.x)));
    v[1] = (yv.y + xv.y * dv.y) * (zv.y / (1.f + __expf(-zv.y)));
    v[2] = (yv.z + xv.z * dv.z) * (zv.z / (1.f + __expf(-zv.z)));
    v[3] = (yv.w + xv.w * dv.w) * (zv.w / (1.f + __expf(-zv.w)));

    __half h[4];
    #pragma unroll
    for (int dd = 0; dd < 4; dd++) h[dd] = __float2half(v[dd]);
    *(uint2*)(ybe + (size_t)r * KE_OUT + d) = *(uint2*)h;
}

// ---------------- launch ----------------
extern "C" void kernel_launch(void* const* d_in, const int* in_sizes, int n_in,
                              void* d_out, int out_size)
{
    const float* hidden     = (const float*)d_in[0];
    const float* in_proj_w  = (const float*)d_in[1];
    const float* conv_w     = (const float*)d_in[2];
    const float* conv_b     = (const float*)d_in[3];
    const float* x_proj_w   = (const float*)d_in[4];
    const float* dt_proj_w  = (const float*)d_in[5];
    const float* dt_proj_b  = (const float*)d_in[6];
    const float* A_log      = (const float*)d_in[7];
    const float* Dvec       = (const float*)d_in[8];
    const float* out_proj_w = (const float*)d_in[9];
    float* out = (float*)d_out;

    float *xz, *xconv, *bc, *xpart, *delta, *y;
    __half *hid_e, *win_e, *xc_e, *xw_e, *dtlo_e, *dtw_e, *yb_e, *ow_e;
    cudaGetSymbolAddress((void**)&xz,    g_xz);
    cudaGetSymbolAddress((void**)&xconv, g_xconv);
    cudaGetSymbolAddress((void**)&bc,    g_bc);
    cudaGetSymbolAddress((void**)&xpart, g_xpart);
    cudaGetSymbolAddress((void**)&delta, g_delta);
    cudaGetSymbolAddress((void**)&y,     g_y);
    cudaGetSymbolAddress((void**)&hid_e, g_hid_e);
    cudaGetSymbolAddress((void**)&win_e, g_win_e);
    cudaGetSymbolAddress((void**)&xc_e,  g_xc_e);
    cudaGetSymbolAddress((void**)&xw_e,  g_xw_e);
    cudaGetSymbolAddress((void**)&dtlo_e,g_dtlo_e);
    cudaGetSymbolAddress((void**)&dtw_e, g_dtw_e);
    cudaGetSymbolAddress((void**)&yb_e,  g_yb_e);
    cudaGetSymbolAddress((void**)&ow_e,  g_ow_e);

    cudaFuncSetAttribute(gemm_mma<0>, cudaFuncAttributeMaxDynamicSharedMemorySize, GEMM_SMEM);
    cudaFuncSetAttribute(gemm_mma<1>, cudaFuncAttributeMaxDynamicSharedMemorySize, GEMM_SMEM);

    // side stream + events, created once (host objects, not device mem)
    static cudaStream_t s_side = nullptr;
    static cudaEvent_t  s_fork = nullptr, s_join1 = nullptr, s_join2 = nullptr;
    if (!s_side) {
        cudaStreamCreateWithFlags(&s_side, cudaStreamNonBlocking);
        cudaEventCreateWithFlags(&s_fork,  cudaEventDisableTiming);
        cudaEventCreateWithFlags(&s_join1, cudaEventDisableTiming);
        cudaEventCreateWithFlags(&s_join2, cudaEventDisableTiming);
    }

    // ---- main: only the conversions the critical path needs first ----
    cvt_w<0><<<dim3(1, NROWS), 256>>>(hidden, DMODEL, DMODEL, hid_e, NROWS);
    cvt_w<0><<<dim3(1, 2 * DINNER), 256>>>(in_proj_w, DMODEL, DMODEL, win_e, 2 * DINNER);

    // ---- fork: side stream does remaining cvts + in_proj z-half GEMM ----
    cudaEventRecord(s_fork, 0);
    cudaStreamWaitEvent(s_side, s_fork, 0);
    cvt_w<1><<<dim3(2, 256), 256, 0, s_side>>>(x_proj_w, DINNER, DINNER, xw_e, XDBL_K);
    cvt_w<1><<<dim3(1, DINNER), 256, 0, s_side>>>(dt_proj_w, DTRANK, DTRANK, dtw_e, DINNER);
    cudaEventRecord(s_join2, s_side);    // xw_e + dtw_e ready
    cvt_w<0><<<dim3(2, DMODEL), 256, 0, s_side>>>(out_proj_w, DINNER, DINNER, ow_e, DMODEL);
    gemm_mma<0><<<dim3(NROWS / BM, DINNER / BN), 256, GEMM_SMEM, s_side>>>(
        hid_e, win_e + (size_t)DINNER * KE_IN, xz + DINNER, 2 * DINNER,
        DINNER, KE_IN, KE_IN / BK, 0, nullptr);
    cudaEventRecord(s_join1, s_side);    // z-half of xz + ow_e ready

    // ---- main critical chain ----
    gemm_mma<0><<<dim3(NROWS / BM, DINNER / BN), 256, GEMM_SMEM>>>(
        hid_e, win_e, xz, 2 * DINNER, DINNER, KE_IN, KE_IN / BK, 0, nullptr);

    conv_silu_kernel<<<(NROWS * DINNER / 4) / 256, 256>>>(xz, conv_w, conv_b, xconv, xc_e);

    cudaStreamWaitEvent(0, s_join2, 0);

    gemm_mma<0><<<dim3(NROWS / BM, 1, XSPLIT), 256, GEMM_SMEM>>>(
        xc_e, xw_e, xpart, XDBL_K, XDBL_K, KE_X, KE_X / BK / XSPLIT,
        (size_t)NROWS * XDBL_K, nullptr);
    reduce_split<<<(NROWS * XDBL_K + 255) / 256, 256>>>(xpart, dtlo_e, bc, NROWS * XDBL_K);

    gemm_mma<1><<<dim3(NROWS / BM, DINNER / BN), 256, GEMM_SMEM>>>(
        dtlo_e, dtw_e, delta, DINNER, DINNER, KE_DT, KE_DT / BK, 0, dt_proj_b);

    scan_kernel<<<(B_SZ * DINNER * DSTATE) / 256, 256>>>(delta, bc, xconv, A_log, y);

    cudaStreamWaitEvent(0, s_join1, 0);

    ymod_kernel<<<(NROWS * DINNER / 4) / 256, 256>>>(y, xconv, Dvec, xz, yb_e);

    gemm_mma<0><<<dim3(NROWS / BM, DMODEL / BN), 256, GEMM_SMEM>>>(
        yb_e, ow_e, out, DMODEL, DMODEL, KE_OUT, KE_OUT / BK, 0, nullptr);
}

// round 16
// speedup vs baseline: 1.0462x; 1.0462x over previous
#include <cuda_runtime.h>
#include <cuda_fp16.h>
#include <math.h>
#include <stdint.h>

// ---------------- problem constants ----------------
#define B_SZ     2
#define L_SZ     1024
#define DMODEL   2048
#define DINNER   4096
#define DSTATE   16
#define DCONV    4
#define DTRANK   128
#define XDBL_K   160
#define NROWS    2048

#define XSPLIT   8             // split-K factor for x_proj

// extended-K sizes
#define KE_IN    DMODEL        // 2048   plain fp16 (1-term)
#define KE_X     (3*DINNER)    // 12288  A [hi|lo|hi], B [hi|hi|lo]
#define KE_DT    (3*DTRANK)    // 384    A [hi|lo|hi], B [hi|hi|lo]
#define KE_OUT   DINNER        // 4096   plain fp16 (1-term)

// ---------------- scratch (__device__ globals, no allocation) ----------------
__device__ float g_xz   [(size_t)NROWS * 2 * DINNER];
__device__ float g_xconv[(size_t)NROWS * DINNER];
__device__ float g_bc   [(size_t)NROWS * 2 * DSTATE];   // interleaved (B,C)
__device__ float g_xpart[(size_t)XSPLIT * NROWS * XDBL_K];
__device__ float g_delta[(size_t)NROWS * DINNER];
__device__ float g_y    [(size_t)NROWS * DINNER];

__device__ __align__(16) __half g_hid_e [(size_t)NROWS    * KE_IN ];
__device__ __align__(16) __half g_win_e [(size_t)2*DINNER * KE_IN ];
__device__ __align__(16) __half g_xc_e  [(size_t)NROWS    * KE_X  ];
__device__ __align__(16) __half g_xw_e  [(size_t)256      * KE_X  ];
__device__ __align__(16) __half g_dtlo_e[(size_t)NROWS    * KE_DT ];
__device__ __align__(16) __half g_dtw_e [(size_t)DINNER   * KE_DT ];
__device__ __align__(16) __half g_yb_e  [(size_t)NROWS    * KE_OUT];
__device__ __align__(16) __half g_ow_e  [(size_t)DMODEL   * KE_OUT];

// ---------------- PTX helpers (baseline ISA: sm_80+ mma.sync / cp.async) ------
__device__ __forceinline__ uint32_t smem_u32(const void* p) {
    uint32_t a;
    asm("{ .reg .u64 t; cvta.to.shared.u64 t, %1; cvt.u32.u64 %0, t; }"
        : "=r"(a) : "l"(p));
    return a;
}

#define CP_ASYNC16(sa, ga) \
    asm volatile("cp.async.cg.shared.global [%0], [%1], 16;" \
                 :: "r"(sa), "l"(ga) : "memory")
#define CP_COMMIT() asm volatile("cp.async.commit_group;" ::: "memory")
#define CP_WAIT(N)  asm volatile("cp.async.wait_group %0;" :: "n"(N) : "memory")

#define LDSM_X4(R0, R1, R2, R3, ADDR) \
    asm volatile("ldmatrix.sync.aligned.m8n8.x4.shared.b16 {%0,%1,%2,%3}, [%4];" \
                 : "=r"(R0), "=r"(R1), "=r"(R2), "=r"(R3) : "r"(ADDR))

#define MMA16816(C, A0, A1, A2, A3, B0, B1) \
    asm volatile("mma.sync.aligned.m16n8k16.row.col.f32.f16.f16.f32 " \
                 "{%0,%1,%2,%3}, {%4,%5,%6,%7}, {%8,%9}, {%0,%1,%2,%3};" \
                 : "+f"((C)[0]), "+f"((C)[1]), "+f"((C)[2]), "+f"((C)[3]) \
                 : "r"(A0), "r"(A1), "r"(A2), "r"(A3), "r"(B0), "r"(B1))

// ---------------- HMMA GEMM: C = A[M,Kext]*B[N,Kext]^T ----------------------
#define BM 128
#define BN 256
#define BK 32
#define STAGES 4
#define LDS_ROW 40
#define A_TILE_BYTES (BM * LDS_ROW * 2)            // 10240
#define B_TILE_BYTES (BN * LDS_ROW * 2)            // 20480
#define STAGE_BYTES  (A_TILE_BYTES + B_TILE_BYTES) // 30720
#define GEMM_SMEM (STAGES * STAGE_BYTES)           // 122880

template<int ACT>
__global__ void __launch_bounds__(256, 1)
gemm_mma(const __half* __restrict__ A,
         const __half* __restrict__ B,
         float* __restrict__ C, int ldc,
         int Nact, int Kext, int kIters, size_t partStride,
         const float* __restrict__ bias)
{
    extern __shared__ char smem[];
    const uint32_t sbase = smem_u32(smem);

    const int t    = threadIdx.x;
    const int lane = t & 31;
    const int wid  = t >> 5;
    const int wm   = wid >> 2;
    const int wn   = wid & 3;
    const int m0   = blockIdx.x * BM;
    const int n0   = blockIdx.y * BN;
    const size_t kbase = (size_t)blockIdx.z * kIters * BK;
    C += (size_t)blockIdx.z * partStride;

    const int ra0 = t >> 2,          ca0 = t & 3;
    const int ra1 = (t + 256) >> 2,  ca1 = (t + 256) & 3;
    const __half* gA0 = A + (size_t)(m0 + ra0) * Kext + kbase + ca0 * 8;
    const __half* gA1 = A + (size_t)(m0 + ra1) * Kext + kbase + ca1 * 8;
    const uint32_t sAo0 = (uint32_t)(ra0 * LDS_ROW * 2 + ca0 * 16);
    const uint32_t sAo1 = (uint32_t)(ra1 * LDS_ROW * 2 + ca1 * 16);
    const __half* gB[4];
    uint32_t sBo[4];
    #pragma unroll
    for (int q = 0; q < 4; q++) {
        int id = t + q * 256;
        int rr = id >> 2, cc = id & 3;
        gB[q]  = B + (size_t)(n0 + rr) * Kext + kbase + cc * 8;
        sBo[q] = (uint32_t)(rr * LDS_ROW * 2 + cc * 16);
    }

    const int g = lane >> 3, r = lane & 7;
    const uint32_t a_off = (uint32_t)((wm * 64 + (g & 1) * 8 + r) * LDS_ROW * 2
                                      + ((g >> 1) * 8) * 2);
    const uint32_t b_off = (uint32_t)((wn * 64 + (g >> 1) * 8 + r) * LDS_ROW * 2
                                      + ((g & 1) * 8) * 2);

    float acc[4][8][4];
    #pragma unroll
    for (int i = 0; i < 4; i++)
        #pragma unroll
        for (int j = 0; j < 8; j++)
            #pragma unroll
            for (int e = 0; e < 4; e++) acc[i][j][e] = 0.f;

    #pragma unroll
    for (int s = 0; s < STAGES - 1; s++) {
        const size_t k0 = (size_t)s * BK;
        const uint32_t st = sbase + s * STAGE_BYTES;
        CP_ASYNC16(st + sAo0, gA0 + k0);
        CP_ASYNC16(st + sAo1, gA1 + k0);
        #pragma unroll
        for (int q = 0; q < 4; q++)
            CP_ASYNC16(st + A_TILE_BYTES + sBo[q], gB[q] + k0);
        CP_COMMIT();
    }

    for (int it = 0; it < kIters; it++) {
        CP_WAIT(STAGES - 2);
        __syncthreads();

        if (it + STAGES - 1 < kIters) {
            const size_t k0 = (size_t)(it + STAGES - 1) * BK;
            const uint32_t st = sbase + ((it + STAGES - 1) % STAGES) * STAGE_BYTES;
            CP_ASYNC16(st + sAo0, gA0 + k0);
            CP_ASYNC16(st + sAo1, gA1 + k0);
            #pragma unroll
            for (int q = 0; q < 4; q++)
                CP_ASYNC16(st + A_TILE_BYTES + sBo[q], gB[q] + k0);
        }
        CP_COMMIT();

        const uint32_t sa  = sbase + (it % STAGES) * STAGE_BYTES;
        const uint32_t sbb = sa + A_TILE_BYTES;
        #pragma unroll
        for (int ks = 0; ks < 2; ks++) {
            uint32_t af[4][4], bfr[4][4];
            #pragma unroll
            for (int i = 0; i < 4; i++)
                LDSM_X4(af[i][0], af[i][1], af[i][2], af[i][3],
                        sa + a_off + ks * 32 + i * (16 * LDS_ROW * 2));
            #pragma unroll
            for (int jp = 0; jp < 4; jp++)
                LDSM_X4(bfr[jp][0], bfr[jp][1], bfr[jp][2], bfr[jp][3],
                        sbb + b_off + ks * 32 + jp * (16 * LDS_ROW * 2));
            #pragma unroll
            for (int i = 0; i < 4; i++)
                #pragma unroll
                for (int j = 0; j < 8; j++)
                    MMA16816(acc[i][j], af[i][0], af[i][1], af[i][2], af[i][3],
                             bfr[j >> 1][(j & 1) * 2], bfr[j >> 1][(j & 1) * 2 + 1]);
        }
    }

    #pragma unroll
    for (int i = 0; i < 4; i++) {
        const int m = m0 + wm * 64 + i * 16 + (lane >> 2);
        #pragma unroll
        for (int j = 0; j < 8; j++) {
            const int n = n0 + wn * 64 + j * 8 + (lane & 3) * 2;
            #pragma unroll
            for (int e = 0; e < 4; e++) {
                const int mm = m + (e >> 1) * 8;
                const int nn = n + (e & 1);
                if (nn < Nact) {
                    float v = acc[i][j][e];
                    if (ACT == 1) {
                        v += bias[nn];
                        v = (v > 20.f) ? v : __logf(1.f + __expf(v));
                    }
                    C[(size_t)mm * ldc + nn] = v;
                }
            }
        }
    }
}

// ---------------- fp32 -> fp16 conversion (vectorized, 8 elems/thread) -------
template<int PAT>
__global__ void cvt_w(const float* __restrict__ in, int ldin, int Kin,
                      __half* __restrict__ out, int R)
{
    int k = (blockIdx.x * blockDim.x + threadIdx.x) * 8;
    int r = blockIdx.y;
    if (k >= Kin) return;
    float v[8];
    if (r < R) {
        float4 a = *(const float4*)(in + (size_t)r * ldin + k);
        float4 b = *(const float4*)(in + (size_t)r * ldin + k + 4);
        v[0]=a.x; v[1]=a.y; v[2]=a.z; v[3]=a.w;
        v[4]=b.x; v[5]=b.y; v[6]=b.z; v[7]=b.w;
    } else {
        #pragma unroll
        for (int j = 0; j < 8; j++) v[j] = 0.f;
    }
    __align__(16) __half h[8];
    #pragma unroll
    for (int j = 0; j < 8; j++) h[j] = __float2half(v[j]);
    if (PAT == 0) {
        *(uint4*)(out + (size_t)r * Kin + k) = *(uint4*)h;
    } else {
        __align__(16) __half l[8];
        #pragma unroll
        for (int j = 0; j < 8; j++) l[j] = __float2half(v[j] - __half2float(h[j]));
        size_t o = (size_t)r * 3 * Kin;
        *(uint4*)(out + o + k)           = *(uint4*)h;
        *(uint4*)(out + o + Kin + k)     = *(uint4*)h;
        *(uint4*)(out + o + 2 * Kin + k) = *(uint4*)l;
    }
}

// ---------------- conv1d + bias + SiLU, x4 vectorized, fused [hi|lo|hi] ------
__global__ void conv_silu_kernel(const float* __restrict__ xz,
                                 const float* __restrict__ cw,
                                 const float* __restrict__ cb,
                                 float* __restrict__ xc,
                                 __half* __restrict__ xce)
{
    int gidx = blockIdx.x * blockDim.x + threadIdx.x;
    int base = gidx * 4;
    int d  = base & (DINNER - 1);
    int bl = base >> 12;
    int l  = bl & (L_SZ - 1);
    int b  = bl >> 10;

    float4 cbv = *(const float4*)(cb + d);
    float a[4] = {cbv.x, cbv.y, cbv.z, cbv.w};
    float4 w[4];
    #pragma unroll
    for (int dd = 0; dd < 4; dd++) w[dd] = *(const float4*)(cw + (d + dd) * DCONV);

    #pragma unroll
    for (int j = 0; j < DCONV; j++) {
        int l2 = l - (DCONV - 1) + j;
        if (l2 >= 0) {
            float4 x4 = *(const float4*)(xz + (size_t)(b * L_SZ + l2) * (2 * DINNER) + d);
            a[0] = fmaf(x4.x, ((const float*)&w[0])[j], a[0]);
            a[1] = fmaf(x4.y, ((const float*)&w[1])[j], a[1]);
            a[2] = fmaf(x4.z, ((const float*)&w[2])[j], a[2]);
            a[3] = fmaf(x4.w, ((const float*)&w[3])[j], a[3]);
        }
    }
    float v[4];
    #pragma unroll
    for (int dd = 0; dd < 4; dd++) v[dd] = a[dd] / (1.f + __expf(-a[dd]));

    *(float4*)(xc + (size_t)bl * DINNER + d) = make_float4(v[0], v[1], v[2], v[3]);

    __half h[4], lo[4];
    #pragma unroll
    for (int dd = 0; dd < 4; dd++) {
        h[dd]  = __float2half(v[dd]);
        lo[dd] = __float2half(v[dd] - __half2float(h[dd]));
    }
    size_t o = (size_t)bl * KE_X + d;
    *(uint2*)(xce + o)              = *(uint2*)h;
    *(uint2*)(xce + o + DINNER)     = *(uint2*)lo;
    *(uint2*)(xce + o + 2 * DINNER) = *(uint2*)h;
}

// ---------------- split-K reduce: emits dt_lo [hi|lo|hi] + interleaved BC ----
__global__ void reduce_split(const float* __restrict__ part,
                             __half* __restrict__ dtlo,
                             float* __restrict__ bc, int n)
{
    int i = blockIdx.x * blockDim.x + threadIdx.x;
    if (i >= n) return;
    float s = 0.f;
    #pragma unroll
    for (int p = 0; p < XSPLIT; p++) s += part[(size_t)p * n + i];
    int r = i / XDBL_K;
    int k = i - r * XDBL_K;
    if (k < DTRANK) {
        __half h = __float2half(s);
        __half lo = __float2half(s - __half2float(h));
        size_t o = (size_t)r * KE_DT + k;
        dtlo[o] = h;
        dtlo[o + DTRANK] = lo;
        dtlo[o + 2 * DTRANK] = h;
    } else if (k < DTRANK + DSTATE) {
        bc[(size_t)r * 2 * DSTATE + 2 * (k - DTRANK)] = s;
    } else {
        bc[(size_t)r * 2 * DSTATE + 2 * (k - DTRANK - DSTATE) + 1] = s;
    }
}

// ---------------- selective scan: 16 lanes/channel, T=4 timestep batching ----
// Verified optimum (R13): the 4-stage shfl butterfly reduces 4 independent
// timestep partials per stage, paying the dependent-latency chain once per
// 4 timesteps. T=1 and T=8 both measured slower.
__global__ void scan_kernel(const float* __restrict__ delta,
                            const float* __restrict__ bc,
                            const float* __restrict__ xconv,
                            const float* __restrict__ A_log,
                            float* __restrict__ y)
{
    int n   = threadIdx.x & 15;
    int grp = (blockIdx.x * blockDim.x + threadIdx.x) >> 4;
    int b   = grp >> 12;
    int d   = grp & (DINNER - 1);

    float a = -expf(A_log[d * DSTATE + n]);
    float h = 0.f;
    size_t base = (size_t)b * L_SZ;
    const float2* bc2 = (const float2*)bc;

    for (int l0 = 0; l0 < L_SZ; l0 += 4) {
        float p[4];
        #pragma unroll
        for (int t = 0; t < 4; t++) {
            size_t r = base + l0 + t;
            float dv = delta[r * DINNER + d];
            float xv = xconv[r * DINNER + d];
            float2 BC = bc2[r * DSTATE + n];

            float dA = __expf(dv * a);
            h = fmaf(h, dA, dv * BC.x * xv);
            p[t] = h * BC.y;
        }
        #pragma unroll
        for (int s = 8; s >= 1; s >>= 1) {
            #pragma unroll
            for (int t = 0; t < 4; t++)
                p[t] += __shfl_xor_sync(0xffffffffu, p[t], s, 16);
        }
        if (n == 0) {
            #pragma unroll
            for (int t = 0; t < 4; t++)
                y[(base + l0 + t) * DINNER + d] = p[t];
        }
    }
}

// ---------------- y = (y + x*D) * silu(z), x4 vectorized, fp16 emit ----------
__global__ void ymod_kernel(const float* __restrict__ y,
                            const float* __restrict__ xconv,
                            const float* __restrict__ Dv,
                            const float* __restrict__ xz,
                            __half* __restrict__ ybe)
{
    int gidx = blockIdx.x * blockDim.x + threadIdx.x;
    int base = gidx * 4;
    int d = base & (DINNER - 1);
    int r = base >> 12;

    float4 zv = *(const float4*)(xz + (size_t)r * (2 * DINNER) + DINNER + d);
    float4 yv = *(const float4*)(y + (size_t)r * DINNER + d);
    float4 xv = *(const float4*)(xconv + (size_t)r * DINNER + d);
    float4 dv = *(const float4*)(Dv + d);

    float v[4];
    v[0] = (yv.x + xv.x * dv.x) * (zv.x / (1.f + __expf(-zv.x)));
    v[1] = (yv.y + xv.y * dv.y) * (zv.y / (1.f + __expf(-zv.y)));
    v[2] = (yv.z + xv.z * dv.z) * (zv.z / (1.f + __expf(-zv.z)));
    v[3] = (yv.w + xv.w * dv.w) * (zv.w / (1.f + __expf(-zv.w)));

    __half h[4];
    #pragma unroll
    for (int dd = 0; dd < 4; dd++) h[dd] = __float2half(v[dd]);
    *(uint2*)(ybe + (size_t)r * KE_OUT + d) = *(uint2*)h;
}

// ---------------- launch ----------------
extern "C" void kernel_launch(void* const* d_in, const int* in_sizes, int n_in,
                              void* d_out, int out_size)
{
    const float* hidden     = (const float*)d_in[0];
    const float* in_proj_w  = (const float*)d_in[1];
    const float* conv_w     = (const float*)d_in[2];
    const float* conv_b     = (const float*)d_in[3];
    const float* x_proj_w   = (const float*)d_in[4];
    const float* dt_proj_w  = (const float*)d_in[5];
    const float* dt_proj_b  = (const float*)d_in[6];
    const float* A_log      = (const float*)d_in[7];
    const float* Dvec       = (const float*)d_in[8];
    const float* out_proj_w = (const float*)d_in[9];
    float* out = (float*)d_out;

    float *xz, *xconv, *bc, *xpart, *delta, *y;
    __half *hid_e, *win_e, *xc_e, *xw_e, *dtlo_e, *dtw_e, *yb_e, *ow_e;
    cudaGetSymbolAddress((void**)&xz,    g_xz);
    cudaGetSymbolAddress((void**)&xconv, g_xconv);
    cudaGetSymbolAddress((void**)&bc,    g_bc);
    cudaGetSymbolAddress((void**)&xpart, g_xpart);
    cudaGetSymbolAddress((void**)&delta, g_delta);
    cudaGetSymbolAddress((void**)&y,     g_y);
    cudaGetSymbolAddress((void**)&hid_e, g_hid_e);
    cudaGetSymbolAddress((void**)&win_e, g_win_e);
    cudaGetSymbolAddress((void**)&xc_e,  g_xc_e);
    cudaGetSymbolAddress((void**)&xw_e,  g_xw_e);
    cudaGetSymbolAddress((void**)&dtlo_e,g_dtlo_e);
    cudaGetSymbolAddress((void**)&dtw_e, g_dtw_e);
    cudaGetSymbolAddress((void**)&yb_e,  g_yb_e);
    cudaGetSymbolAddress((void**)&ow_e,  g_ow_e);

    cudaFuncSetAttribute(gemm_mma<0>, cudaFuncAttributeMaxDynamicSharedMemorySize, GEMM_SMEM);
    cudaFuncSetAttribute(gemm_mma<1>, cudaFuncAttributeMaxDynamicSharedMemorySize, GEMM_SMEM);

    // side stream + events, created once (host objects, not device mem)
    static cudaStream_t s_side = nullptr;
    static cudaEvent_t  s_fork = nullptr, s_join1 = nullptr, s_join2 = nullptr;
    if (!s_side) {
        cudaStreamCreateWithFlags(&s_side, cudaStreamNonBlocking);
        cudaEventCreateWithFlags(&s_fork,  cudaEventDisableTiming);
        cudaEventCreateWithFlags(&s_join1, cudaEventDisableTiming);
        cudaEventCreateWithFlags(&s_join2, cudaEventDisableTiming);
    }

    // ---- main: only the conversions the critical path needs first ----
    cvt_w<0><<<dim3(1, NROWS), 256>>>(hidden, DMODEL, DMODEL, hid_e, NROWS);
    cvt_w<0><<<dim3(1, 2 * DINNER), 256>>>(in_proj_w, DMODEL, DMODEL, win_e, 2 * DINNER);

    // ---- fork: side stream does remaining cvts + in_proj z-half GEMM ----
    cudaEventRecord(s_fork, 0);
    cudaStreamWaitEvent(s_side, s_fork, 0);
    cvt_w<1><<<dim3(2, 256), 256, 0, s_side>>>(x_proj_w, DINNER, DINNER, xw_e, XDBL_K);
    cvt_w<1><<<dim3(1, DINNER), 256, 0, s_side>>>(dt_proj_w, DTRANK, DTRANK, dtw_e, DINNER);
    cudaEventRecord(s_join2, s_side);    // xw_e + dtw_e ready
    cvt_w<0><<<dim3(2, DMODEL), 256, 0, s_side>>>(out_proj_w, DINNER, DINNER, ow_e, DMODEL);
    gemm_mma<0><<<dim3(NROWS / BM, DINNER / BN), 256, GEMM_SMEM, s_side>>>(
        hid_e, win_e + (size_t)DINNER * KE_IN, xz + DINNER, 2 * DINNER,
        DINNER, KE_IN, KE_IN / BK, 0, nullptr);
    cudaEventRecord(s_join1, s_side);    // z-half of xz + ow_e ready

    // ---- main critical chain ----
    gemm_mma<0><<<dim3(NROWS / BM, DINNER / BN), 256, GEMM_SMEM>>>(
        hid_e, win_e, xz, 2 * DINNER, DINNER, KE_IN, KE_IN / BK, 0, nullptr);

    conv_silu_kernel<<<(NROWS * DINNER / 4) / 256, 256>>>(xz, conv_w, conv_b, xconv, xc_e);

    cudaStreamWaitEvent(0, s_join2, 0);

    gemm_mma<0><<<dim3(NROWS / BM, 1, XSPLIT), 256, GEMM_SMEM>>>(
        xc_e, xw_e, xpart, XDBL_K, XDBL_K, KE_X, KE_X / BK / XSPLIT,
        (size_t)NROWS * XDBL_K, nullptr);
    reduce_split<<<(NROWS * XDBL_K + 255) / 256, 256>>>(xpart, dtlo_e, bc, NROWS * XDBL_K);

    gemm_mma<1><<<dim3(NROWS / BM, DINNER / BN), 256, GEMM_SMEM>>>(
        dtlo_e, dtw_e, delta, DINNER, DINNER, KE_DT, KE_DT / BK, 0, dt_proj_b);

    scan_kernel<<<(B_SZ * DINNER * DSTATE) / 256, 256>>>(delta, bc, xconv, A_log, y);

    cudaStreamWaitEvent(0, s_join1, 0);

    ymod_kernel<<<(NROWS * DINNER / 4) / 256, 256>>>(y, xconv, Dvec, xz, yb_e);

    gemm_mma<0><<<dim3(NROWS / BM, DMODEL / BN), 256, GEMM_SMEM>>>(
        yb_e, ow_e, out, DMODEL, DMODEL, KE_OUT, KE_OUT / BK, 0, nullptr);
}

// round 17
// speedup vs baseline: 1.0767x; 1.0292x over previous
#include <cuda_runtime.h>
#include <cuda_fp16.h>
#include <math.h>
#include <stdint.h>

// ---------------- problem constants ----------------
#define B_SZ     2
#define L_SZ     1024
#define DMODEL   2048
#define DINNER   4096
#define DSTATE   16
#define DCONV    4
#define DTRANK   128
#define XDBL_K   160
#define NROWS    2048

#define XSPLIT   8             // split-K factor for x_proj

// extended-K sizes
#define KE_IN    DMODEL        // 2048   plain fp16 (1-term)
#define KE_X     (2*DINNER)    // 8192   A [hi|lo], B [hi|hi]  (2-term)
#define KE_DT    (2*DTRANK)    // 256    A [hi|lo], B [hi|hi]  (2-term)
#define KE_OUT   DINNER        // 4096   plain fp16 (1-term)

// ---------------- scratch (__device__ globals, no allocation) ----------------
__device__ float g_xz   [(size_t)NROWS * 2 * DINNER];
__device__ float g_xconv[(size_t)NROWS * DINNER];
__device__ float g_bc   [(size_t)NROWS * 2 * DSTATE];   // interleaved (B,C)
__device__ float g_xpart[(size_t)XSPLIT * NROWS * XDBL_K];
__device__ float g_delta[(size_t)NROWS * DINNER];
__device__ float g_y    [(size_t)NROWS * DINNER];

__device__ __align__(16) __half g_hid_e [(size_t)NROWS    * KE_IN ];
__device__ __align__(16) __half g_win_e [(size_t)2*DINNER * KE_IN ];
__device__ __align__(16) __half g_xc_e  [(size_t)NROWS    * KE_X  ];
__device__ __align__(16) __half g_xw_e  [(size_t)256      * KE_X  ];
__device__ __align__(16) __half g_dtlo_e[(size_t)NROWS    * KE_DT ];
__device__ __align__(16) __half g_dtw_e [(size_t)DINNER   * KE_DT ];
__device__ __align__(16) __half g_yb_e  [(size_t)NROWS    * KE_OUT];
__device__ __align__(16) __half g_ow_e  [(size_t)DMODEL   * KE_OUT];

// ---------------- PTX helpers (baseline ISA: sm_80+ mma.sync / cp.async) ------
__device__ __forceinline__ uint32_t smem_u32(const void* p) {
    uint32_t a;
    asm("{ .reg .u64 t; cvta.to.shared.u64 t, %1; cvt.u32.u64 %0, t; }"
        : "=r"(a) : "l"(p));
    return a;
}

#define CP_ASYNC16(sa, ga) \
    asm volatile("cp.async.cg.shared.global [%0], [%1], 16;" \
                 :: "r"(sa), "l"(ga) : "memory")
#define CP_COMMIT() asm volatile("cp.async.commit_group;" ::: "memory")
#define CP_WAIT(N)  asm volatile("cp.async.wait_group %0;" :: "n"(N) : "memory")

#define LDSM_X4(R0, R1, R2, R3, ADDR) \
    asm volatile("ldmatrix.sync.aligned.m8n8.x4.shared.b16 {%0,%1,%2,%3}, [%4];" \
                 : "=r"(R0), "=r"(R1), "=r"(R2), "=r"(R3) : "r"(ADDR))

#define MMA16816(C, A0, A1, A2, A3, B0, B1) \
    asm volatile("mma.sync.aligned.m16n8k16.row.col.f32.f16.f16.f32 " \
                 "{%0,%1,%2,%3}, {%4,%5,%6,%7}, {%8,%9}, {%0,%1,%2,%3};" \
                 : "+f"((C)[0]), "+f"((C)[1]), "+f"((C)[2]), "+f"((C)[3]) \
                 : "r"(A0), "r"(A1), "r"(A2), "r"(A3), "r"(B0), "r"(B1))

// ---------------- HMMA GEMM: C = A[M,Kext]*B[N,Kext]^T ----------------------
#define BM 128
#define BN 256
#define BK 32
#define STAGES 4
#define LDS_ROW 40
#define A_TILE_BYTES (BM * LDS_ROW * 2)            // 10240
#define B_TILE_BYTES (BN * LDS_ROW * 2)            // 20480
#define STAGE_BYTES  (A_TILE_BYTES + B_TILE_BYTES) // 30720
#define GEMM_SMEM (STAGES * STAGE_BYTES)           // 122880

template<int ACT>
__global__ void __launch_bounds__(256, 1)
gemm_mma(const __half* __restrict__ A,
         const __half* __restrict__ B,
         float* __restrict__ C, int ldc,
         int Nact, int Kext, int kIters, size_t partStride,
         const float* __restrict__ bias)
{
    extern __shared__ char smem[];
    const uint32_t sbase = smem_u32(smem);

    const int t    = threadIdx.x;
    const int lane = t & 31;
    const int wid  = t >> 5;
    const int wm   = wid >> 2;
    const int wn   = wid & 3;
    const int m0   = blockIdx.x * BM;
    const int n0   = blockIdx.y * BN;
    const size_t kbase = (size_t)blockIdx.z * kIters * BK;
    C += (size_t)blockIdx.z * partStride;

    const int ra0 = t >> 2,          ca0 = t & 3;
    const int ra1 = (t + 256) >> 2,  ca1 = (t + 256) & 3;
    const __half* gA0 = A + (size_t)(m0 + ra0) * Kext + kbase + ca0 * 8;
    const __half* gA1 = A + (size_t)(m0 + ra1) * Kext + kbase + ca1 * 8;
    const uint32_t sAo0 = (uint32_t)(ra0 * LDS_ROW * 2 + ca0 * 16);
    const uint32_t sAo1 = (uint32_t)(ra1 * LDS_ROW * 2 + ca1 * 16);
    const __half* gB[4];
    uint32_t sBo[4];
    #pragma unroll
    for (int q = 0; q < 4; q++) {
        int id = t + q * 256;
        int rr = id >> 2, cc = id & 3;
        gB[q]  = B + (size_t)(n0 + rr) * Kext + kbase + cc * 8;
        sBo[q] = (uint32_t)(rr * LDS_ROW * 2 + cc * 16);
    }

    const int g = lane >> 3, r = lane & 7;
    const uint32_t a_off = (uint32_t)((wm * 64 + (g & 1) * 8 + r) * LDS_ROW * 2
                                      + ((g >> 1) * 8) * 2);
    const uint32_t b_off = (uint32_t)((wn * 64 + (g >> 1) * 8 + r) * LDS_ROW * 2
                                      + ((g & 1) * 8) * 2);

    float acc[4][8][4];
    #pragma unroll
    for (int i = 0; i < 4; i++)
        #pragma unroll
        for (int j = 0; j < 8; j++)
            #pragma unroll
            for (int e = 0; e < 4; e++) acc[i][j][e] = 0.f;

    #pragma unroll
    for (int s = 0; s < STAGES - 1; s++) {
        const size_t k0 = (size_t)s * BK;
        const uint32_t st = sbase + s * STAGE_BYTES;
        CP_ASYNC16(st + sAo0, gA0 + k0);
        CP_ASYNC16(st + sAo1, gA1 + k0);
        #pragma unroll
        for (int q = 0; q < 4; q++)
            CP_ASYNC16(st + A_TILE_BYTES + sBo[q], gB[q] + k0);
        CP_COMMIT();
    }

    for (int it = 0; it < kIters; it++) {
        CP_WAIT(STAGES - 2);
        __syncthreads();

        if (it + STAGES - 1 < kIters) {
            const size_t k0 = (size_t)(it + STAGES - 1) * BK;
            const uint32_t st = sbase + ((it + STAGES - 1) % STAGES) * STAGE_BYTES;
            CP_ASYNC16(st + sAo0, gA0 + k0);
            CP_ASYNC16(st + sAo1, gA1 + k0);
            #pragma unroll
            for (int q = 0; q < 4; q++)
                CP_ASYNC16(st + A_TILE_BYTES + sBo[q], gB[q] + k0);
        }
        CP_COMMIT();

        const uint32_t sa  = sbase + (it % STAGES) * STAGE_BYTES;
        const uint32_t sbb = sa + A_TILE_BYTES;
        #pragma unroll
        for (int ks = 0; ks < 2; ks++) {
            uint32_t af[4][4], bfr[4][4];
            #pragma unroll
            for (int i = 0; i < 4; i++)
                LDSM_X4(af[i][0], af[i][1], af[i][2], af[i][3],
                        sa + a_off + ks * 32 + i * (16 * LDS_ROW * 2));
            #pragma unroll
            for (int jp = 0; jp < 4; jp++)
                LDSM_X4(bfr[jp][0], bfr[jp][1], bfr[jp][2], bfr[jp][3],
                        sbb + b_off + ks * 32 + jp * (16 * LDS_ROW * 2));
            #pragma unroll
            for (int i = 0; i < 4; i++)
                #pragma unroll
                for (int j = 0; j < 8; j++)
                    MMA16816(acc[i][j], af[i][0], af[i][1], af[i][2], af[i][3],
                             bfr[j >> 1][(j & 1) * 2], bfr[j >> 1][(j & 1) * 2 + 1]);
        }
    }

    #pragma unroll
    for (int i = 0; i < 4; i++) {
        const int m = m0 + wm * 64 + i * 16 + (lane >> 2);
        #pragma unroll
        for (int j = 0; j < 8; j++) {
            const int n = n0 + wn * 64 + j * 8 + (lane & 3) * 2;
            #pragma unroll
            for (int e = 0; e < 4; e++) {
                const int mm = m + (e >> 1) * 8;
                const int nn = n + (e & 1);
                if (nn < Nact) {
                    float v = acc[i][j][e];
                    if (ACT == 1) {
                        v += bias[nn];
                        v = (v > 20.f) ? v : __logf(1.f + __expf(v));
                    }
                    C[(size_t)mm * ldc + nn] = v;
                }
            }
        }
    }
}

// ---------------- fp32 -> fp16 conversion (vectorized, 8 elems/thread) -------
// PAT 0: [hi] (1-term).  PAT 2: [hi|hi] (2-term B operand).
// Rows beyond R are zero-padded.
template<int PAT>
__global__ void cvt_w(const float* __restrict__ in, int ldin, int Kin,
                      __half* __restrict__ out, int R)
{
    int k = (blockIdx.x * blockDim.x + threadIdx.x) * 8;
    int r = blockIdx.y;
    if (k >= Kin) return;
    float v[8];
    if (r < R) {
        float4 a = *(const float4*)(in + (size_t)r * ldin + k);
        float4 b = *(const float4*)(in + (size_t)r * ldin + k + 4);
        v[0]=a.x; v[1]=a.y; v[2]=a.z; v[3]=a.w;
        v[4]=b.x; v[5]=b.y; v[6]=b.z; v[7]=b.w;
    } else {
        #pragma unroll
        for (int j = 0; j < 8; j++) v[j] = 0.f;
    }
    __align__(16) __half h[8];
    #pragma unroll
    for (int j = 0; j < 8; j++) h[j] = __float2half(v[j]);
    if (PAT == 0) {
        *(uint4*)(out + (size_t)r * Kin + k) = *(uint4*)h;
    } else {
        size_t o = (size_t)r * 2 * Kin;
        *(uint4*)(out + o + k)       = *(uint4*)h;
        *(uint4*)(out + o + Kin + k) = *(uint4*)h;
    }
}

// ---------------- conv1d + bias + SiLU, x4 vectorized, fused [hi|lo] emit ----
__global__ void conv_silu_kernel(const float* __restrict__ xz,
                                 const float* __restrict__ cw,
                                 const float* __restrict__ cb,
                                 float* __restrict__ xc,
                                 __half* __restrict__ xce)
{
    int gidx = blockIdx.x * blockDim.x + threadIdx.x;
    int base = gidx * 4;
    int d  = base & (DINNER - 1);
    int bl = base >> 12;
    int l  = bl & (L_SZ - 1);
    int b  = bl >> 10;

    float4 cbv = *(const float4*)(cb + d);
    float a[4] = {cbv.x, cbv.y, cbv.z, cbv.w};
    float4 w[4];
    #pragma unroll
    for (int dd = 0; dd < 4; dd++) w[dd] = *(const float4*)(cw + (d + dd) * DCONV);

    #pragma unroll
    for (int j = 0; j < DCONV; j++) {
        int l2 = l - (DCONV - 1) + j;
        if (l2 >= 0) {
            float4 x4 = *(const float4*)(xz + (size_t)(b * L_SZ + l2) * (2 * DINNER) + d);
            a[0] = fmaf(x4.x, ((const float*)&w[0])[j], a[0]);
            a[1] = fmaf(x4.y, ((const float*)&w[1])[j], a[1]);
            a[2] = fmaf(x4.z, ((const float*)&w[2])[j], a[2]);
            a[3] = fmaf(x4.w, ((const float*)&w[3])[j], a[3]);
        }
    }
    float v[4];
    #pragma unroll
    for (int dd = 0; dd < 4; dd++) v[dd] = a[dd] / (1.f + __expf(-a[dd]));

    *(float4*)(xc + (size_t)bl * DINNER + d) = make_float4(v[0], v[1], v[2], v[3]);

    __half h[4], lo[4];
    #pragma unroll
    for (int dd = 0; dd < 4; dd++) {
        h[dd]  = __float2half(v[dd]);
        lo[dd] = __float2half(v[dd] - __half2float(h[dd]));
    }
    size_t o = (size_t)bl * KE_X + d;
    *(uint2*)(xce + o)          = *(uint2*)h;
    *(uint2*)(xce + o + DINNER) = *(uint2*)lo;
}

// ---------------- split-K reduce: emits dt_lo [hi|lo] + interleaved BC -------
__global__ void reduce_split(const float* __restrict__ part,
                             __half* __restrict__ dtlo,
                             float* __restrict__ bc, int n)
{
    int i = blockIdx.x * blockDim.x + threadIdx.x;
    if (i >= n) return;
    float s = 0.f;
    #pragma unroll
    for (int p = 0; p < XSPLIT; p++) s += part[(size_t)p * n + i];
    int r = i / XDBL_K;
    int k = i - r * XDBL_K;
    if (k < DTRANK) {
        __half h = __float2half(s);
        __half lo = __float2half(s - __half2float(h));
        size_t o = (size_t)r * KE_DT + k;
        dtlo[o] = h;
        dtlo[o + DTRANK] = lo;
    } else if (k < DTRANK + DSTATE) {
        bc[(size_t)r * 2 * DSTATE + 2 * (k - DTRANK)] = s;
    } else {
        bc[(size_t)r * 2 * DSTATE + 2 * (k - DTRANK - DSTATE) + 1] = s;
    }
}

// ---------------- selective scan: 16 lanes/channel, T=4 timestep batching ----
// Verified optimum (R13).
__global__ void scan_kernel(const float* __restrict__ delta,
                            const float* __restrict__ bc,
                            const float* __restrict__ xconv,
                            const float* __restrict__ A_log,
                            float* __restrict__ y)
{
    int n   = threadIdx.x & 15;
    int grp = (blockIdx.x * blockDim.x + threadIdx.x) >> 4;
    int b   = grp >> 12;
    int d   = grp & (DINNER - 1);

    float a = -expf(A_log[d * DSTATE + n]);
    float h = 0.f;
    size_t base = (size_t)b * L_SZ;
    const float2* bc2 = (const float2*)bc;

    for (int l0 = 0; l0 < L_SZ; l0 += 4) {
        float p[4];
        #pragma unroll
        for (int t = 0; t < 4; t++) {
            size_t r = base + l0 + t;
            float dv = delta[r * DINNER + d];
            float xv = xconv[r * DINNER + d];
            float2 BC = bc2[r * DSTATE + n];

            float dA = __expf(dv * a);
            h = fmaf(h, dA, dv * BC.x * xv);
            p[t] = h * BC.y;
        }
        #pragma unroll
        for (int s = 8; s >= 1; s >>= 1) {
            #pragma unroll
            for (int t = 0; t < 4; t++)
                p[t] += __shfl_xor_sync(0xffffffffu, p[t], s, 16);
        }
        if (n == 0) {
            #pragma unroll
            for (int t = 0; t < 4; t++)
                y[(base + l0 + t) * DINNER + d] = p[t];
        }
    }
}

// ---------------- y = (y + x*D) * silu(z), x4 vectorized, fp16 emit ----------
__global__ void ymod_kernel(const float* __restrict__ y,
                            const float* __restrict__ xconv,
                            const float* __restrict__ Dv,
                            const float* __restrict__ xz,
                            __half* __restrict__ ybe)
{
    int gidx = blockIdx.x * blockDim.x + threadIdx.x;
    int base = gidx * 4;
    int d = base & (DINNER - 1);
    int r = base >> 12;

    float4 zv = *(const float4*)(xz + (size_t)r * (2 * DINNER) + DINNER + d);
    float4 yv = *(const float4*)(y + (size_t)r * DINNER + d);
    float4 xv = *(const float4*)(xconv + (size_t)r * DINNER + d);
    float4 dv = *(const float4*)(Dv + d);

    float v[4];
    v[0] = (yv.x + xv.x * dv.x) * (zv.x / (1.f + __expf(-zv.x)));
    v[1] = (yv.y + xv.y * dv.y) * (zv.y / (1.f + __expf(-zv.y)));
    v[2] = (yv.z + xv.z * dv.z) * (zv.z / (1.f + __expf(-zv.z)));
    v[3] = (yv.w + xv.w * dv.w) * (zv.w / (1.f + __expf(-zv.w)));

    __half h[4];
    #pragma unroll
    for (int dd = 0; dd < 4; dd++) h[dd] = __float2half(v[dd]);
    *(uint2*)(ybe + (size_t)r * KE_OUT + d) = *(uint2*)h;
}

// ---------------- launch ----------------
extern "C" void kernel_launch(void* const* d_in, const int* in_sizes, int n_in,
                              void* d_out, int out_size)
{
    const float* hidden     = (const float*)d_in[0];
    const float* in_proj_w  = (const float*)d_in[1];
    const float* conv_w     = (const float*)d_in[2];
    const float* conv_b     = (const float*)d_in[3];
    const float* x_proj_w   = (const float*)d_in[4];
    const float* dt_proj_w  = (const float*)d_in[5];
    const float* dt_proj_b  = (const float*)d_in[6];
    const float* A_log      = (const float*)d_in[7];
    const float* Dvec       = (const float*)d_in[8];
    const float* out_proj_w = (const float*)d_in[9];
    float* out = (float*)d_out;

    float *xz, *xconv, *bc, *xpart, *delta, *y;
    __half *hid_e, *win_e, *xc_e, *xw_e, *dtlo_e, *dtw_e, *yb_e, *ow_e;
    cudaGetSymbolAddress((void**)&xz,    g_xz);
    cudaGetSymbolAddress((void**)&xconv, g_xconv);
    cudaGetSymbolAddress((void**)&bc,    g_bc);
    cudaGetSymbolAddress((void**)&xpart, g_xpart);
    cudaGetSymbolAddress((void**)&delta, g_delta);
    cudaGetSymbolAddress((void**)&y,     g_y);
    cudaGetSymbolAddress((void**)&hid_e, g_hid_e);
    cudaGetSymbolAddress((void**)&win_e, g_win_e);
    cudaGetSymbolAddress((void**)&xc_e,  g_xc_e);
    cudaGetSymbolAddress((void**)&xw_e,  g_xw_e);
    cudaGetSymbolAddress((void**)&dtlo_e,g_dtlo_e);
    cudaGetSymbolAddress((void**)&dtw_e, g_dtw_e);
    cudaGetSymbolAddress((void**)&yb_e,  g_yb_e);
    cudaGetSymbolAddress((void**)&ow_e,  g_ow_e);

    cudaFuncSetAttribute(gemm_mma<0>, cudaFuncAttributeMaxDynamicSharedMemorySize, GEMM_SMEM);
    cudaFuncSetAttribute(gemm_mma<1>, cudaFuncAttributeMaxDynamicSharedMemorySize, GEMM_SMEM);

    // side stream + events, created once (host objects, not device mem)
    static cudaStream_t s_side = nullptr;
    static cudaEvent_t  s_fork = nullptr, s_join1 = nullptr, s_join2 = nullptr;
    if (!s_side) {
        cudaStreamCreateWithFlags(&s_side, cudaStreamNonBlocking);
        cudaEventCreateWithFlags(&s_fork,  cudaEventDisableTiming);
        cudaEventCreateWithFlags(&s_join1, cudaEventDisableTiming);
        cudaEventCreateWithFlags(&s_join2, cudaEventDisableTiming);
    }

    // ---- main: only the conversions the critical path needs first ----
    cvt_w<0><<<dim3(1, NROWS), 256>>>(hidden, DMODEL, DMODEL, hid_e, NROWS);
    cvt_w<0><<<dim3(1, 2 * DINNER), 256>>>(in_proj_w, DMODEL, DMODEL, win_e, 2 * DINNER);

    // ---- fork: side stream does remaining cvts + in_proj z-half GEMM ----
    cudaEventRecord(s_fork, 0);
    cudaStreamWaitEvent(s_side, s_fork, 0);
    cvt_w<2><<<dim3(2, 256), 256, 0, s_side>>>(x_proj_w, DINNER, DINNER, xw_e, XDBL_K);
    cvt_w<2><<<dim3(1, DINNER), 256, 0, s_side>>>(dt_proj_w, DTRANK, DTRANK, dtw_e, DINNER);
    cudaEventRecord(s_join2, s_side);    // xw_e + dtw_e ready
    cvt_w<0><<<dim3(2, DMODEL), 256, 0, s_side>>>(out_proj_w, DINNER, DINNER, ow_e, DMODEL);
    gemm_mma<0><<<dim3(NROWS / BM, DINNER / BN), 256, GEMM_SMEM, s_side>>>(
        hid_e, win_e + (size_t)DINNER * KE_IN, xz + DINNER, 2 * DINNER,
        DINNER, KE_IN, KE_IN / BK, 0, nullptr);
    cudaEventRecord(s_join1, s_side);    // z-half of xz + ow_e ready

    // ---- main critical chain ----
    gemm_mma<0><<<dim3(NROWS / BM, DINNER / BN), 256, GEMM_SMEM>>>(
        hid_e, win_e, xz, 2 * DINNER, DINNER, KE_IN, KE_IN / BK, 0, nullptr);

    conv_silu_kernel<<<(NROWS * DINNER / 4) / 256, 256>>>(xz, conv_w, conv_b, xconv, xc_e);

    cudaStreamWaitEvent(0, s_join2, 0);

    gemm_mma<0><<<dim3(NROWS / BM, 1, XSPLIT), 256, GEMM_SMEM>>>(
        xc_e, xw_e, xpart, XDBL_K, XDBL_K, KE_X, KE_X / BK / XSPLIT,
        (size_t)NROWS * XDBL_K, nullptr);
    reduce_split<<<(NROWS * XDBL_K + 255) / 256, 256>>>(xpart, dtlo_e, bc, NROWS * XDBL_K);

    gemm_mma<1><<<dim3(NROWS / BM, DINNER / BN), 256, GEMM_SMEM>>>(
        dtlo_e, dtw_e, delta, DINNER, DINNER, KE_DT, KE_DT / BK, 0, dt_proj_b);

    scan_kernel<<<(B_SZ * DINNER * DSTATE) / 256, 256>>>(delta, bc, xconv, A_log, y);

    cudaStreamWaitEvent(0, s_join1, 0);

    ymod_kernel<<<(NROWS * DINNER / 4) / 256, 256>>>(y, xconv, Dvec, xz, yb_e);

    gemm_mma<0><<<dim3(NROWS / BM, DMODEL / BN), 256, GEMM_SMEM>>>(
        yb_e, ow_e, out, DMODEL, DMODEL, KE_OUT, KE_OUT / BK, 0, nullptr);
}